// round 1
// baseline (speedup 1.0000x reference)
#include <cuda_runtime.h>

#define NW 8
#define NL 6
#define FULL 0xffffffffu

// Fused weight matrices: SU(2), store only first row (C00r, C00i, C01r, C01i)
__device__ float4 g_C[NL * NW];

__global__ void precompute_C(const float* __restrict__ w) {
    int tid = threadIdx.x;
    if (tid >= NL * NW) return;
    float c0, s0, c1, s1, cz, sz;
    sincosf(0.5f * w[tid * 3 + 0], &s0, &c0);   // Rx
    sincosf(0.5f * w[tid * 3 + 1], &s1, &c1);   // Ry
    sincosf(0.5f * w[tid * 3 + 2], &sz, &cz);   // Rz
    // A = Ry * Rx (row 0)
    float A00r = c1 * c0, A00i = s1 * s0;
    float A01r = -s1 * c0, A01i = -c1 * s0;
    // C = Rz * A : row0 *= (cz - i sz)
    g_C[tid] = make_float4(cz * A00r + sz * A00i,
                           cz * A00i - sz * A00r,
                           cz * A01r + sz * A01i,
                           cz * A01i - sz * A01r);
}

// One warp per batch element. Lane holds amplitudes n = lane*8 + t.
// Index bit b (0..7) <-> wire (7-b). Bits 0-2 = register index t (wires 7,6,5),
// bits 3-7 = lane bits 0-4 (wires 4,3,2,1,0).
__global__ void __launch_bounds__(256) qnn_kernel(const float* __restrict__ x,
                                                  float* __restrict__ out, int B) {
    __shared__ float4 sC[NL * NW];
    for (int k = threadIdx.x; k < NL * NW; k += blockDim.x) sC[k] = g_C[k];
    __syncthreads();

    int warp = (blockIdx.x * blockDim.x + threadIdx.x) >> 5;
    int lane = threadIdx.x & 31;
    if (warp >= B) return;

    float se, ce, so, co;
    sincosf(0.5f * x[2 * warp + 0], &se, &ce);  // RX encoding (even wires)
    sincosf(0.5f * x[2 * warp + 1], &so, &co);  // RY encoding (odd wires)

    float sr[8], si[8];
#pragma unroll
    for (int t = 0; t < 8; t++) { sr[t] = 0.f; si[t] = 0.f; }
    if (lane == 0) sr[0] = 1.0f;

    for (int layer = 0; layer < NL; layer++) {
        // --- fused single-qubit gate per wire: M = C * E(x) (SU(2)) ---
#pragma unroll
        for (int wire = 0; wire < 8; wire++) {
            float4 C = sC[layer * 8 + wire];
            float m00r, m00i, m01r, m01i;
            if ((wire & 1) == 0) {
                // E = RX(x0): [[ce, -i se],[-i se, ce]]
                m00r =  C.x * ce + C.w * se;
                m00i =  C.y * ce - C.z * se;
                m01r =  C.y * se + C.z * ce;
                m01i = -C.x * se + C.w * ce;
            } else {
                // E = RY(x1): [[co, -so],[so, co]]
                m00r =  C.x * co + C.z * so;
                m00i =  C.y * co + C.w * so;
                m01r = -C.x * so + C.z * co;
                m01i = -C.y * so + C.w * co;
            }
            if (wire >= 5) {
                // register-local wire: pair t <-> t|mask
                const int mask = 1 << (7 - wire);
#pragma unroll
                for (int t = 0; t < 8; t++) {
                    if (t & mask) continue;
                    const int u = t | mask;
                    float ar = sr[t], ai = si[t], br = sr[u], bi = si[u];
                    sr[t] =  m00r * ar - m00i * ai + m01r * br - m01i * bi;
                    si[t] =  m00r * ai + m00i * ar + m01r * bi + m01i * br;
                    // m10 = (-m01r, m01i), m11 = (m00r, -m00i)
                    sr[u] = -m01r * ar - m01i * ai + m00r * br + m00i * bi;
                    si[u] = -m01r * ai + m01i * ar + m00r * bi - m00i * br;
                }
            } else {
                // lane-level wire: exchange with partner lane via shfl.xor
                const int lmask = 1 << (4 - wire);
                float sg = (lane & lmask) ? -1.f : 1.f;
                // result = P*own + Q*other; P,Q uniform per lane
                float Pr = m00r,      Pi = sg * m00i;
                float Qr = sg * m01r, Qi = m01i;
#pragma unroll
                for (int t = 0; t < 8; t++) {
                    float orr = __shfl_xor_sync(FULL, sr[t], lmask);
                    float oii = __shfl_xor_sync(FULL, si[t], lmask);
                    float ar = sr[t], ai = si[t];
                    sr[t] = Pr * ar - Pi * ai + Qr * orr - Qi * oii;
                    si[t] = Pr * ai + Pi * ar + Qr * oii + Qi * orr;
                }
            }
        }
        // --- CNOT chain ---
        // CNOT(0,1)..CNOT(3,4) are lane-bit CNOTs: compose into ONE permutation.
        // Inverse map (src for my lane): apply inverse chain in reverse order.
        {
            int src = lane;
            src ^= (src >> 1) & 1;   // undo CNOT(3,4): bit0 ^= bit1
            src ^= (src >> 1) & 2;   // undo CNOT(2,3)
            src ^= (src >> 1) & 4;   // undo CNOT(1,2)
            src ^= (src >> 1) & 8;   // undo CNOT(0,1)
#pragma unroll
            for (int t = 0; t < 8; t++) {
                sr[t] = __shfl_sync(FULL, sr[t], src);
                si[t] = __shfl_sync(FULL, si[t], src);
            }
        }
        // CNOT(4,5): control = lane bit0, target = reg bit2
        {
            bool ctl = (lane & 1) != 0;
#pragma unroll
            for (int k = 0; k < 4; k++) {
                float ar = sr[k], ai = si[k], br = sr[k + 4], bi = si[k + 4];
                sr[k]     = ctl ? br : ar;  si[k]     = ctl ? bi : ai;
                sr[k + 4] = ctl ? ar : br;  si[k + 4] = ctl ? ai : bi;
            }
        }
        // CNOT(5,6): control reg bit2, target reg bit1: swap (4,6),(5,7)
        {
            float tr;
            tr = sr[4]; sr[4] = sr[6]; sr[6] = tr;  tr = si[4]; si[4] = si[6]; si[6] = tr;
            tr = sr[5]; sr[5] = sr[7]; sr[7] = tr;  tr = si[5]; si[5] = si[7]; si[7] = tr;
        }
        // CNOT(6,7): control reg bit1, target reg bit0: swap (2,3),(6,7)
        {
            float tr;
            tr = sr[2]; sr[2] = sr[3]; sr[3] = tr;  tr = si[2]; si[2] = si[3]; si[3] = tr;
            tr = sr[6]; sr[6] = sr[7]; sr[7] = tr;  tr = si[6]; si[6] = si[7]; si[7] = tr;
        }
    }

    // --- expectation values <Z_i> ---
    float p[8];
#pragma unroll
    for (int t = 0; t < 8; t++) p[t] = sr[t] * sr[t] + si[t] * si[t];

    float ev[8];
    float tot = ((p[0] + p[1]) + (p[2] + p[3])) + ((p[4] + p[5]) + (p[6] + p[7]));
    // wires 0..4: sign from lane bit (4-i)
#pragma unroll
    for (int i = 0; i < 5; i++)
        ev[i] = (lane & (1 << (4 - i))) ? -tot : tot;
    // wires 5,6,7: sign from reg bits 2,1,0
    ev[5] = (p[0] + p[1] + p[2] + p[3]) - (p[4] + p[5] + p[6] + p[7]);
    ev[6] = (p[0] + p[1] + p[4] + p[5]) - (p[2] + p[3] + p[6] + p[7]);
    ev[7] = (p[0] + p[2] + p[4] + p[6]) - (p[1] + p[3] + p[5] + p[7]);

#pragma unroll
    for (int off = 16; off > 0; off >>= 1) {
#pragma unroll
        for (int i = 0; i < 8; i++)
            ev[i] += __shfl_xor_sync(FULL, ev[i], off);
    }

    if (lane == 0) {
        const float PI = 3.14159265358979f;
        ((float4*)out)[warp * 2 + 0] = make_float4(ev[0] * PI, ev[1] * PI, ev[2] * PI, ev[3] * PI);
        ((float4*)out)[warp * 2 + 1] = make_float4(ev[4] * PI, ev[5] * PI, ev[6] * PI, ev[7] * PI);
    }
}

extern "C" void kernel_launch(void* const* d_in, const int* in_sizes, int n_in,
                              void* d_out, int out_size) {
    const float* x = (const float*)d_in[0];        // [B, 2]
    const float* w = (const float*)d_in[1];        // [6, 8, 3]
    float* out = (float*)d_out;                    // [B, 8]
    int B = in_sizes[0] / 2;

    precompute_C<<<1, 64>>>(w);
    int threads = 256;
    int blocks = (B * 32 + threads - 1) / threads;
    qnn_kernel<<<blocks, threads>>>(x, out, B);
}

// round 2
// speedup vs baseline: 1.3211x; 1.3211x over previous
#include <cuda_runtime.h>

#define FULL 0xffffffffu
typedef unsigned long long u64;

// ---------- packed f32x2 helpers ----------
__device__ __forceinline__ u64 pk(float lo, float hi) {
    u64 r; asm("mov.b64 %0, {%1,%2};" : "=l"(r) : "f"(lo), "f"(hi)); return r;
}
__device__ __forceinline__ u64 pk2(float v) { return pk(v, v); }
__device__ __forceinline__ void upk(u64 a, float& lo, float& hi) {
    asm("mov.b64 {%0,%1}, %2;" : "=f"(lo), "=f"(hi) : "l"(a));
}
__device__ __forceinline__ u64 fma2(u64 a, u64 b, u64 c) {
    u64 d; asm("fma.rn.f32x2 %0, %1, %2, %3;" : "=l"(d) : "l"(a), "l"(b), "l"(c)); return d;
}
__device__ __forceinline__ u64 mul2(u64 a, u64 b) {
    u64 d; asm("mul.rn.f32x2 %0, %1, %2;" : "=l"(d) : "l"(a), "l"(b)); return d;
}
__device__ __forceinline__ u64 swp(u64 a) { float l, h; upk(a, l, h); return pk(h, l); }
__device__ __forceinline__ u64 shfx(u64 a, int m) {
    float l, h; upk(a, l, h);
    return pk(__shfl_xor_sync(FULL, l, m), __shfl_xor_sync(FULL, h, m));
}
__device__ __forceinline__ u64 shfi(u64 a, int s) {
    float l, h; upk(a, l, h);
    return pk(__shfl_sync(FULL, l, s), __shfl_sync(FULL, h, s));
}

// Per gate (layer*8+wire): packed rows of fused weight matrix C = Rz*Ry*Rx (SU(2)).
// x = (C00r,C00i), y = (C01r,C01i), z = (C01i,-C01r), w = (C00i,-C00r)
__device__ ulonglong4 g_G[48];

__global__ void precompute_G(const float* __restrict__ w) {
    int tid = threadIdx.x;
    if (tid >= 48) return;
    float c0, s0, c1, s1, cz, sz;
    sincosf(0.5f * w[tid * 3 + 0], &s0, &c0);   // Rx
    sincosf(0.5f * w[tid * 3 + 1], &s1, &c1);   // Ry
    sincosf(0.5f * w[tid * 3 + 2], &sz, &cz);   // Rz
    float A00r = c1 * c0,  A00i = s1 * s0;
    float A01r = -s1 * c0, A01i = -c1 * s0;
    float C00r = cz * A00r + sz * A00i;
    float C00i = cz * A00i - sz * A00r;
    float C01r = cz * A01r + sz * A01i;
    float C01i = cz * A01i - sz * A01r;
    ulonglong4 G;
    G.x = pk(C00r, C00i);
    G.y = pk(C01r, C01i);
    G.z = pk(C01i, -C01r);
    G.w = pk(C00i, -C00r);
    g_G[tid] = G;
}

// Fused gate matrix M = C*E(x): returns packed m00=(m00r,m00i), m01=(m01r,m01i).
__device__ __forceinline__ void gate_m(const ulonglong4& G, int wire,
                                       u64 ce2, u64 se2, u64 co2, u64 so2, u64 nso2,
                                       u64& m00p, u64& m01p) {
    if ((wire & 1) == 0) {   // RX encoding
        m00p = fma2(ce2, G.x, mul2(se2, G.z));
        m01p = fma2(ce2, G.y, mul2(se2, G.w));
    } else {                 // RY encoding
        m00p = fma2(co2, G.x, mul2(so2, G.y));
        m01p = fma2(co2, G.y, mul2(nso2, G.x));
    }
}

// One warp per batch element. Amplitude n: lane bits 4..0 = n bits 7..3
// (wires 0..4), reg index t bits 2..0 = n bits 2..0 (wires 5,6,7).
// State packed SoA along t-bit0 (wire7): pr[j]=(re[2j],re[2j+1]), pi[j] same.
__global__ void __launch_bounds__(256) qnn_kernel(const float* __restrict__ x,
                                                  float* __restrict__ out, int B) {
    __shared__ ulonglong4 sG[48];
    for (int k = threadIdx.x; k < 48; k += blockDim.x) sG[k] = g_G[k];
    __syncthreads();

    int warp = (blockIdx.x * blockDim.x + threadIdx.x) >> 5;
    int lane = threadIdx.x & 31;
    if (warp >= B) return;

    float se, ce, so, co;
    sincosf(0.5f * x[2 * warp + 0], &se, &ce);  // RX enc (even wires)
    sincosf(0.5f * x[2 * warp + 1], &so, &co);  // RY enc (odd wires)
    u64 ce2 = pk2(ce), se2 = pk2(se), co2 = pk2(co), so2 = pk2(so), nso2 = pk2(-so);

    // ---------- layer 0: product state built directly from |0..0> ----------
    float g0r[8], g0i[8], g1r[8], g1i[8];   // column 0 of each M: m00 and m10=-conj(m01)
#pragma unroll
    for (int wv = 0; wv < 8; wv++) {
        u64 m00p, m01p;
        gate_m(sG[wv], wv, ce2, se2, co2, so2, nso2, m00p, m01p);
        float r0, i0, r1, i1;
        upk(m00p, r0, i0); upk(m01p, r1, i1);
        g0r[wv] = r0;  g0i[wv] = i0;
        g1r[wv] = -r1; g1i[wv] = i1;
    }
    // prefix over lane wires 0..4
    float cr = 1.f, ci = 0.f;
#pragma unroll
    for (int wv = 0; wv < 5; wv++) {
        bool b = (lane >> (4 - wv)) & 1;
        float fr = b ? g1r[wv] : g0r[wv];
        float fi = b ? g1i[wv] : g0i[wv];
        float nr = cr * fr - ci * fi;
        float ni = cr * fi + ci * fr;
        cr = nr; ci = ni;
    }
    // expand register wires 5 (t bit2), 6 (bit1), 7 (bit0)
    float ar[8], ai[8];
    {
        float d0r = cr * g0r[5] - ci * g0i[5], d0i = cr * g0i[5] + ci * g0r[5];
        float d1r = cr * g1r[5] - ci * g1i[5], d1i = cr * g1i[5] + ci * g1r[5];
        float e0r[4], e0i[4];
        e0r[0] = d0r * g0r[6] - d0i * g0i[6]; e0i[0] = d0r * g0i[6] + d0i * g0r[6]; // b5=0,b6=0
        e0r[1] = d0r * g1r[6] - d0i * g1i[6]; e0i[1] = d0r * g1i[6] + d0i * g1r[6]; // b5=0,b6=1
        e0r[2] = d1r * g0r[6] - d1i * g0i[6]; e0i[2] = d1r * g0i[6] + d1i * g0r[6]; // b5=1,b6=0
        e0r[3] = d1r * g1r[6] - d1i * g1i[6]; e0i[3] = d1r * g1i[6] + d1i * g1r[6]; // b5=1,b6=1
#pragma unroll
        for (int t = 0; t < 8; t++) {
            int e = t >> 1;
            bool b7 = t & 1;
            float fr = b7 ? g1r[7] : g0r[7];
            float fi = b7 ? g1i[7] : g0i[7];
            ar[t] = e0r[e] * fr - e0i[e] * fi;
            ai[t] = e0r[e] * fi + e0i[e] * fr;
        }
    }
    u64 pr[4], pi[4];
#pragma unroll
    for (int j = 0; j < 4; j++) {
        pr[j] = pk(ar[2 * j], ar[2 * j + 1]);
        pi[j] = pk(ai[2 * j], ai[2 * j + 1]);
    }

    // layer-0 CNOT chain + layers 1..5 (gates + CNOTs)
    for (int layer = 0; layer < 6; layer++) {
        if (layer > 0) {
#pragma unroll
            for (int wire = 0; wire < 8; wire++) {
                u64 m00p, m01p;
                gate_m(sG[layer * 8 + wire], wire, ce2, se2, co2, so2, nso2, m00p, m01p);
                float m00r, m00i, m01r, m01i;
                upk(m00p, m00r, m00i); upk(m01p, m01r, m01i);

                if (wire < 5) {
                    // lane-level butterfly via shfl.xor
                    const int lm = 1 << (4 - wire);
                    bool neg = (lane & lm) != 0;
                    float Piv = neg ? -m00i : m00i;
                    float Qrv = neg ? -m01r : m01r;
                    u64 Pr2 = pk2(m00r), Pi2 = pk2(Piv), nPi2 = pk2(-Piv);
                    u64 Qr2 = pk2(Qrv), Qi2 = pk2(m01i), nQi2 = pk2(-m01i);
#pragma unroll
                    for (int j = 0; j < 4; j++) {
                        u64 opr = shfx(pr[j], lm);
                        u64 opi = shfx(pi[j], lm);
                        u64 nr = fma2(Pr2, pr[j], fma2(nPi2, pi[j], fma2(Qr2, opr, mul2(nQi2, opi))));
                        u64 ni = fma2(Pi2, pr[j], fma2(Pr2, pi[j], fma2(Qi2, opr, mul2(Qr2, opi))));
                        pr[j] = nr; pi[j] = ni;
                    }
                } else if (wire < 7) {
                    // inter-register packed butterfly (wire5: stride 2; wire6: stride 1)
                    u64 r00 = pk2(m00r), i00 = pk2(m00i), ni00 = pk2(-m00i);
                    u64 r01 = pk2(m01r), nr01 = pk2(-m01r), i01 = pk2(m01i), ni01 = pk2(-m01i);
                    const int off = (wire == 5) ? 2 : 1;
#pragma unroll
                    for (int j = 0; j < 4; j++) {
                        if (j & off) continue;
                        int k = j | off;
                        u64 pA = pr[j], qA = pi[j], pB = pr[k], qB = pi[k];
                        pr[j] = fma2(r00, pA, fma2(ni00, qA, fma2(r01, pB, mul2(ni01, qB))));
                        pi[j] = fma2(i00, pA, fma2(r00, qA, fma2(i01, pB, mul2(r01, qB))));
                        pr[k] = fma2(nr01, pA, fma2(ni01, qA, fma2(r00, pB, mul2(i00, qB))));
                        pi[k] = fma2(i01, pA, fma2(nr01, qA, fma2(ni00, pB, mul2(r00, qB))));
                    }
                } else {
                    // wire7: intra-register butterfly with half-swaps
                    u64 A = pk2(m00r);
                    u64 Bc = pk(m01r, -m01r);
                    u64 Cc = pk(-m00i, m00i);
                    u64 D = pk2(-m01i);
                    u64 E = pk(m00i, -m00i);
                    u64 F = pk2(m01i);
#pragma unroll
                    for (int j = 0; j < 4; j++) {
                        u64 spr = swp(pr[j]), spi = swp(pi[j]);
                        u64 nr = fma2(A, pr[j], fma2(Bc, spr, fma2(Cc, pi[j], mul2(D, spi))));
                        u64 ni = fma2(E, pr[j], fma2(F, spr, fma2(A, pi[j], mul2(Bc, spi))));
                        pr[j] = nr; pi[j] = ni;
                    }
                }
            }
        }

        // ---- CNOT chain ----
        // CNOT(0,1)..CNOT(3,4): composed lane permutation
        {
            int src = lane;
            src ^= (src >> 1) & 1;
            src ^= (src >> 1) & 2;
            src ^= (src >> 1) & 4;
            src ^= (src >> 1) & 8;
#pragma unroll
            for (int j = 0; j < 4; j++) {
                pr[j] = shfi(pr[j], src);
                pi[j] = shfi(pi[j], src);
            }
        }
        // CNOT(4,5): control lane bit0, target reg bit2
        {
            bool ctl = (lane & 1) != 0;
#pragma unroll
            for (int k = 0; k < 2; k++) {
                u64 a = pr[k], b = pr[k + 2];
                pr[k] = ctl ? b : a; pr[k + 2] = ctl ? a : b;
                u64 c = pi[k], d = pi[k + 2];
                pi[k] = ctl ? d : c; pi[k + 2] = ctl ? c : d;
            }
        }
        // CNOT(5,6): swap reg pair 2<->3 (t: 4<->6, 5<->7)
        {
            u64 t;
            t = pr[2]; pr[2] = pr[3]; pr[3] = t;
            t = pi[2]; pi[2] = pi[3]; pi[3] = t;
        }
        // CNOT(6,7): swap halves of regs 1 and 3 (t: 2<->3, 6<->7)
        pr[1] = swp(pr[1]); pr[3] = swp(pr[3]);
        pi[1] = swp(pi[1]); pi[3] = swp(pi[3]);
    }

    // ---------- expectation values ----------
    float p[8];
#pragma unroll
    for (int j = 0; j < 4; j++) {
        u64 pp = fma2(pr[j], pr[j], mul2(pi[j], pi[j]));
        upk(pp, p[2 * j], p[2 * j + 1]);
    }

    float ev[8];
    float tot = ((p[0] + p[1]) + (p[2] + p[3])) + ((p[4] + p[5]) + (p[6] + p[7]));
#pragma unroll
    for (int i = 0; i < 5; i++)
        ev[i] = (lane & (1 << (4 - i))) ? -tot : tot;
    ev[5] = (p[0] + p[1] + p[2] + p[3]) - (p[4] + p[5] + p[6] + p[7]);
    ev[6] = (p[0] + p[1] + p[4] + p[5]) - (p[2] + p[3] + p[6] + p[7]);
    ev[7] = (p[0] + p[2] + p[4] + p[6]) - (p[1] + p[3] + p[5] + p[7]);

#pragma unroll
    for (int off = 16; off > 0; off >>= 1) {
#pragma unroll
        for (int i = 0; i < 8; i++)
            ev[i] += __shfl_xor_sync(FULL, ev[i], off);
    }

    if (lane == 0) {
        const float PI = 3.14159265358979f;
        ((float4*)out)[warp * 2 + 0] = make_float4(ev[0] * PI, ev[1] * PI, ev[2] * PI, ev[3] * PI);
        ((float4*)out)[warp * 2 + 1] = make_float4(ev[4] * PI, ev[5] * PI, ev[6] * PI, ev[7] * PI);
    }
}

extern "C" void kernel_launch(void* const* d_in, const int* in_sizes, int n_in,
                              void* d_out, int out_size) {
    const float* x = (const float*)d_in[0];   // [B, 2]
    const float* w = (const float*)d_in[1];   // [6, 8, 3]
    float* out = (float*)d_out;               // [B, 8]
    int B = in_sizes[0] / 2;

    precompute_G<<<1, 64>>>(w);
    int threads = 256;
    int blocks = (B * 32 + threads - 1) / threads;
    qnn_kernel<<<blocks, threads>>>(x, out, B);
}